// round 5
// baseline (speedup 1.0000x reference)
#include <cuda_runtime.h>

// BilateralBlur: barrier-free streaming separable depth-guided blur, 2 px/thread.
// B=8, H=1024, W=1024, R=2 (K=5). Block = 128 threads x 2 px = 256 columns.
// 36 stream rows per 32-row strip: prologue(4) + 6 chunks of 5 + epilogue(2),
// all ring slots compile-time. Interior strips: no row checks, pointer induction.

#define HDIM 1024
#define WDIM 1024
#define BATCH 8
#define NT 128
#define PX 2
#define TILEW (NT * PX)     // 256
#define HSTRIP 32

__device__ __forceinline__ float f_ex2(float x){ float y; asm("ex2.approx.ftz.f32 %0, %1;" : "=f"(y) : "f"(x)); return y; }
__device__ __forceinline__ float f_lg2(float x){ float y; asm("lg2.approx.ftz.f32 %0, %1;" : "=f"(y) : "f"(x)); return y; }
__device__ __forceinline__ float f_rcp(float x){ float y; asm("rcp.approx.ftz.f32 %0, %1;" : "=f"(y) : "f"(x)); return y; }

__global__ __launch_bounds__(NT, 5)
void bilat_px2s_kernel(const float* __restrict__ bright,
                       const float* __restrict__ dark,
                       const float* __restrict__ depths,
                       const float* __restrict__ s_dv,
                       const float* __restrict__ s_sv,
                       const float* __restrict__ s_de,
                       const float* __restrict__ s_eps,
                       const float* __restrict__ s_ce,
                       float* __restrict__ out)
{
    const float L2E = 1.4426950408889634f;
    const float dv  = __ldg(s_dv);
    const float sv  = __ldg(s_sv);
    const float de  = __ldg(s_de);
    const float eps = __ldg(s_eps);
    const float ce  = __ldg(s_ce);
    const float c1  = -L2E / (2.0f * dv);     // depth weight exponent coeff (log2)
    const float q1  = -L2E / (2.0f * sv);     // spatial log2 weight |off|=1
    const float q4  = 4.0f * q1;              // |off|=2
    const float lgeps = f_lg2(eps);           // eps > 0

    const int tid  = threadIdx.x;
    const int col0 = blockIdx.x * TILEW + tid * PX;
    const int y0   = blockIdx.y * HSTRIP;
    const int base = blockIdx.z * (HDIM * WDIM);

    const bool lv = (col0 != 0);
    const bool rv = (col0 + PX < WDIM);
    const int offL = lv ? -2 : 0;
    const int offR = rv ?  2 : 0;

    float2 rz[5], riz[5], rbx[5], rdx[5];     // ring: stream row m -> slot m%5

    // emission-side pointers (output row y0.., always valid rows)
    const float* pbc = bright + base + y0 * WDIM + col0;
    const float* pdc = dark   + base + y0 * WDIM + col0;
    float*       po  = out    + base + y0 * WDIM + col0;

    // horizontal blur core on 6 taps -> ring slot S (compile-time after inline)
    auto hcore = [&](int S, float2 zL, float2 zC, float2 zR,
                     float2 bL, float2 bC, float2 bR,
                     float2 dL, float2 dC, float2 dR, bool rowv)
    {
        float z6[6], b6[6], d6[6];
        z6[0] = (rowv & lv) ? zL.x : 0.f;  z6[1] = (rowv & lv) ? zL.y : 0.f;
        z6[2] = rowv ? zC.x : 0.f;         z6[3] = rowv ? zC.y : 0.f;
        z6[4] = (rowv & rv) ? zR.x : 0.f;  z6[5] = (rowv & rv) ? zR.y : 0.f;
        b6[0] = bL.x; b6[1] = bL.y; b6[2] = bC.x; b6[3] = bC.y; b6[4] = bR.x; b6[5] = bR.y;
        d6[0] = dL.x; d6[1] = dL.y; d6[2] = dC.x; d6[3] = dC.y; d6[4] = dR.x; d6[5] = dR.y;

        float bx[PX], dx[PX], izp[PX];
        #pragma unroll
        for (int p = 0; p < PX; p++) {
            const float iz = f_rcp(z6[2 + p]);
            izp[p] = iz;
            float ws = 1.f, bs = b6[2 + p], ds = d6[2 + p];   // center tap weight == 1
            #pragma unroll
            for (int k = 0; k < 5; k++) {
                if (k == 2) continue;
                const float sw = (k == 0 || k == 4) ? q4 : q1;
                float rel = fminf(fabsf(fmaf(z6[p + k], iz, -1.f)), 1.f);
                float w = f_ex2(fmaf(rel * rel, c1, sw));
                ws += w;
                bs = fmaf(w, b6[p + k], bs);
                ds = fmaf(w, d6[p + k], ds);
            }
            const float r = f_rcp(ws);
            bx[p] = rowv ? bs * r : 0.f;      // keep NaN out for pad rows
            dx[p] = rowv ? ds * r : 0.f;
        }
        rz[S]  = make_float2(z6[2], z6[3]);
        riz[S] = make_float2(izp[0], izp[1]);
        rbx[S] = make_float2(bx[0], bx[1]);
        rdx[S] = make_float2(dx[0], dx[1]);
    };

    // vertical blur + blend for stream row m (S = m%5); output row advances po.
    auto emit = [&](int S)
    {
        const int sc = (S + 3) % 5;           // center slot (stream row m-2)
        const float2 bC = __ldg((const float2*)pbc);
        const float2 dC = __ldg((const float2*)pdc);
        float res[PX];
        #pragma unroll
        for (int p = 0; p < PX; p++) {
            const float izc = p ? riz[sc].y : riz[sc].x;
            float vws = 1.f;
            float vbs = p ? rbx[sc].y : rbx[sc].x;
            float vds = p ? rdx[sc].y : rdx[sc].x;
            #pragma unroll
            for (int j = 0; j < 5; j++) {
                if (j == 2) continue;
                const int sj = (S + 1 + j) % 5;
                const float sw = (j == 0 || j == 4) ? q4 : q1;
                const float zj = p ? rz[sj].y : rz[sj].x;
                float rel = fminf(fabsf(fmaf(zj, izc, -1.f)), 1.f);
                float w = f_ex2(fmaf(rel * rel, c1, sw));
                vws += w;
                vbs = fmaf(w, p ? rbx[sj].y : rbx[sj].x, vbs);
                vds = fmaf(w, p ? rdx[sj].y : rdx[sj].x, vds);
            }
            const float vr = f_rcp(vws);
            const float bm = vbs * vr, dm = vds * vr;
            const float b = p ? bC.y : bC.x;
            const float d = p ? dC.y : dC.x;

            // t = devb/devd; devd = max(pow,eps) folded via ex2-monotonicity
            const float lb  = f_lg2(fmaxf(fabsf(b - bm), 1e-8f));
            const float ld  = f_lg2(fmaxf(fabsf(d - dm), 1e-8f));
            const float ld2 = fmaxf(de * ld, lgeps);
            const float t   = ce * f_ex2(fmaf(de, lb, -ld2));
            const float s   = f_rcp(1.f + t);
            res[p] = fmaf(t, d, b) * s;
        }
        *reinterpret_cast<float2*>(po) = make_float2(res[0], res[1]);
        pbc += WDIM; pdc += WDIM; po += WDIM;
    };

    if (blockIdx.y > 0 && blockIdx.y + 1 < gridDim.y) {
        // -------- interior strips: all 36 stream rows in-bounds --------
        const float* pz = depths + base + (y0 - 2) * WDIM + col0;
        const float* pb = bright + base + (y0 - 2) * WDIM + col0;
        const float* pd = dark   + base + (y0 - 2) * WDIM + col0;

        auto hrow = [&](int S) {
            const float2 zL = __ldg((const float2*)(pz + offL));
            const float2 zC = __ldg((const float2*)pz);
            const float2 zR = __ldg((const float2*)(pz + offR));
            const float2 bL = __ldg((const float2*)(pb + offL));
            const float2 bC = __ldg((const float2*)pb);
            const float2 bR = __ldg((const float2*)(pb + offR));
            const float2 dL = __ldg((const float2*)(pd + offL));
            const float2 dC = __ldg((const float2*)pd);
            const float2 dR = __ldg((const float2*)(pd + offR));
            hcore(S, zL, zC, zR, bL, bC, bR, dL, dC, dR, true);
            pz += WDIM; pb += WDIM; pd += WDIM;
        };

        hrow(0); hrow(1); hrow(2); hrow(3);       // prologue m=0..3
        #pragma unroll 1
        for (int t = 0; t < 6; t++) {             // m = 4+5t .. 8+5t
            hrow(4); emit(4);
            hrow(0); emit(0);
            hrow(1); emit(1);
            hrow(2); emit(2);
            hrow(3); emit(3);
        }
        hrow(4); emit(4);                         // m=34
        hrow(0); emit(0);                         // m=35
    } else {
        // -------- border strips (top/bottom): per-row validity --------
        auto hrow_chk = [&](int S, int m) {
            const int gy = y0 - 2 + m;
            const bool rowv = ((unsigned)gy) < (unsigned)HDIM;
            const int gyc = rowv ? gy : (gy < 0 ? 0 : HDIM - 1);
            const int ro = base + gyc * WDIM + col0;
            const float* qz = depths + ro;
            const float* qb = bright + ro;
            const float* qd = dark   + ro;
            const float2 zL = __ldg((const float2*)(qz + offL));
            const float2 zC = __ldg((const float2*)qz);
            const float2 zR = __ldg((const float2*)(qz + offR));
            const float2 bL = __ldg((const float2*)(qb + offL));
            const float2 bC = __ldg((const float2*)qb);
            const float2 bR = __ldg((const float2*)(qb + offR));
            const float2 dL = __ldg((const float2*)(qd + offL));
            const float2 dC = __ldg((const float2*)qd);
            const float2 dR = __ldg((const float2*)(qd + offR));
            hcore(S, zL, zC, zR, bL, bC, bR, dL, dC, dR, rowv);
        };

        hrow_chk(0, 0); hrow_chk(1, 1); hrow_chk(2, 2); hrow_chk(3, 3);
        #pragma unroll 1
        for (int t = 0; t < 6; t++) {
            const int m = 4 + 5 * t;
            hrow_chk(4, m + 0); emit(4);
            hrow_chk(0, m + 1); emit(0);
            hrow_chk(1, m + 2); emit(1);
            hrow_chk(2, m + 3); emit(2);
            hrow_chk(3, m + 4); emit(3);
        }
        hrow_chk(4, 34); emit(4);
        hrow_chk(0, 35); emit(0);
    }
}

extern "C" void kernel_launch(void* const* d_in, const int* in_sizes, int n_in,
                              void* d_out, int out_size)
{
    const float* bright = (const float*)d_in[0];
    const float* dark   = (const float*)d_in[1];
    const float* depths = (const float*)d_in[2];
    const float* dv     = (const float*)d_in[3];
    const float* sv     = (const float*)d_in[4];
    const float* de     = (const float*)d_in[5];
    const float* eps    = (const float*)d_in[6];
    const float* ce     = (const float*)d_in[7];
    float* out = (float*)d_out;

    dim3 grid(WDIM / TILEW, HDIM / HSTRIP, BATCH);
    bilat_px2s_kernel<<<grid, NT>>>(bright, dark, depths, dv, sv, de, eps, ce, out);
}